// round 1
// baseline (speedup 1.0000x reference)
#include <cuda_runtime.h>
#include <math.h>

namespace {

constexpr int Bb  = 8;
constexpr int Hh  = 112;
constexpr int Ww  = 112;
constexpr int C   = 192;
constexpr int NH  = 6;
constexpr int HD  = 32;      // C / NH
constexpr int WS  = 7;
constexpr int SS  = 3;
constexpr int N   = 49;      // WS*WS
constexpr int WG  = Hh / WS; // 16
constexpr int NW  = WG * WG; // 256
constexpr int BW  = Bb * NW; // 2048
constexpr int T   = BW * N;  // 100352 tokens
constexpr int C4  = 4 * C;   // 768
constexpr float EPS    = 1e-5f;
constexpr float LOG100 = 4.605170185988091f;

// ---------------- scratch (static device globals; no allocation) -----------
__device__ float g_win [(size_t)T * C];   // gathered windows; later attn output
__device__ float g_q   [(size_t)T * C];   // q; later proj output
__device__ float g_k   [(size_t)T * C];   // k; later hidden
__device__ float g_v   [(size_t)T * C];   // v; later mlp output
__device__ float g_mlp1[(size_t)T * C4];  // fc1 output
__device__ float g_cpb [169 * NH];        // CPB MLP output table (169 x NH)
__device__ float g_scl [NH];              // per-head logit scale

// ---------------- CPB bias table MLP: (169,2)->512(relu)->NH ---------------
__global__ void cpb_kernel(const float* __restrict__ w0, const float* __restrict__ b0,
                           const float* __restrict__ w1, const float* __restrict__ ls) {
    int r   = blockIdx.x;     // 0..168
    int tid = threadIdx.x;    // 256 threads
    __shared__ float part[256][NH];

    int ri = r / 13, rj = r % 13;
    float t0 = (ri - 6) * (8.0f / 6.0f);
    float t1 = (rj - 6) * (8.0f / 6.0f);
    float v0 = copysignf(log2f(fabsf(t0) + 1.0f) * (1.0f / 3.0f), t0);
    float v1 = copysignf(log2f(fabsf(t1) + 1.0f) * (1.0f / 3.0f), t1);

    float acc[NH];
    #pragma unroll
    for (int h = 0; h < NH; ++h) acc[h] = 0.0f;
    for (int j = tid; j < 512; j += 256) {
        float hv = fmaxf(v0 * w0[j] + v1 * w0[512 + j] + b0[j], 0.0f);
        #pragma unroll
        for (int h = 0; h < NH; ++h) acc[h] += hv * w1[j * NH + h];
    }
    #pragma unroll
    for (int h = 0; h < NH; ++h) part[tid][h] = acc[h];
    __syncthreads();
    if (tid < NH) {
        float s = 0.0f;
        for (int i = 0; i < 256; ++i) s += part[i][tid];
        g_cpb[r * NH + tid] = s;
        if (r == 0) g_scl[tid] = expf(fminf(ls[tid], LOG100));
    }
}

// ---------------- cyclic shift + window partition gather -------------------
__global__ void gather_kernel(const float* __restrict__ x) {
    int t  = blockIdx.x;          // window-layout token
    int bw = t / N, n = t % N;
    int b  = bw / NW, w_ = bw % NW;
    int wy = w_ / WG, wx = w_ % WG;
    int hh = wy * WS + n / WS, ww = wx * WS + n % WS;
    int oh = (hh + SS) % Hh, ow = (ww + SS) % Ww;
    size_t src = ((size_t)(b * Hh + oh) * Ww + ow) * C;
    g_win[(size_t)t * C + threadIdx.x] = x[src + threadIdx.x];
}

// ---------------- fp32 SGEMM: C = act(A@B + bias) --------------------------
// A: MxK row-major, B: KxN row-major. M%128==0, N%64==0, K%16==0.
constexpr int BM = 128, BN = 64, BK = 16, TM = 8, TN = 8;

__device__ __forceinline__ float gelu_tanh(float v) {
    return 0.5f * v * (1.0f + tanhf(0.7978845608028654f * (v + 0.044715f * v * v * v)));
}

__global__ __launch_bounds__(128, 4)
void sgemm_kernel(const float* __restrict__ A, const float* __restrict__ B,
                  const float* __restrict__ bias, float* __restrict__ Cmat,
                  int M, int Nn, int K, int act) {
    __shared__ float As[BK][BM + 1];
    __shared__ float Bs[BK][BN];

    int tid = threadIdx.x;                 // 0..127
    int bm  = blockIdx.y * BM;
    int bn  = blockIdx.x * BN;
    int trow = (tid >> 3) * TM;            // 16 groups of 8
    int tcol = (tid & 7) * TN;

    float acc[TM][TN];
    #pragma unroll
    for (int i = 0; i < TM; ++i)
        #pragma unroll
        for (int j = 0; j < TN; ++j) acc[i][j] = 0.0f;

    for (int kt = 0; kt < K; kt += BK) {
        #pragma unroll
        for (int i = 0; i < 4; ++i) {              // A tile: 128x16
            int idx = tid + i * 128;
            int row = idx >> 2;
            int k4  = (idx & 3) * 4;
            float4 a = *reinterpret_cast<const float4*>(
                &A[(size_t)(bm + row) * K + kt + k4]);
            As[k4 + 0][row] = a.x; As[k4 + 1][row] = a.y;
            As[k4 + 2][row] = a.z; As[k4 + 3][row] = a.w;
        }
        #pragma unroll
        for (int i = 0; i < 2; ++i) {              // B tile: 16x64
            int idx = tid + i * 128;
            int row = idx >> 4;
            int c4  = (idx & 15) * 4;
            *reinterpret_cast<float4*>(&Bs[row][c4]) =
                *reinterpret_cast<const float4*>(&B[(size_t)(kt + row) * Nn + bn + c4]);
        }
        __syncthreads();
        #pragma unroll
        for (int kk = 0; kk < BK; ++kk) {
            float af[TM], bf[TN];
            #pragma unroll
            for (int i = 0; i < TM; ++i) af[i] = As[kk][trow + i];
            #pragma unroll
            for (int j = 0; j < TN; ++j) bf[j] = Bs[kk][tcol + j];
            #pragma unroll
            for (int i = 0; i < TM; ++i)
                #pragma unroll
                for (int j = 0; j < TN; ++j) acc[i][j] += af[i] * bf[j];
        }
        __syncthreads();
    }

    #pragma unroll
    for (int i = 0; i < TM; ++i) {
        size_t rbase = (size_t)(bm + trow + i) * Nn + bn + tcol;
        #pragma unroll
        for (int j = 0; j < TN; ++j) {
            float v = acc[i][j];
            if (bias) v += bias[bn + tcol + j];
            if (act == 1) v = gelu_tanh(v);
            Cmat[rbase + j] = v;
        }
    }
}

// ---------------- fused per-(window,head) attention -------------------------
__global__ __launch_bounds__(256)
void attn_kernel() {
    int blk = blockIdx.x;          // 0..BW*NH-1
    int bw  = blk / NH, h = blk % NH;
    int tid = threadIdx.x;

    __shared__ float qs[N * HD], ks[N * HD], vs[N * HD];
    __shared__ float lg[N * N];
    __shared__ int   rgn[N];
    __shared__ float scale_s;

    if (tid == 0) scale_s = g_scl[h];

    for (int e = tid; e < N * HD; e += blockDim.x) {
        int n = e / HD, d = e % HD;
        size_t base = (size_t)(bw * N + n) * C + h * HD + d;
        qs[e] = g_q[base]; ks[e] = g_k[base]; vs[e] = g_v[base];
    }
    if (tid < N) {
        int w_ = bw % NW, wy = w_ / WG, wx = w_ % WG;
        int gh = wy * WS + tid / WS, gw = wx * WS + tid % WS;
        int rh = gh < Hh - WS ? 0 : (gh < Hh - SS ? 1 : 2);
        int rw = gw < Ww - WS ? 0 : (gw < Ww - SS ? 1 : 2);
        rgn[tid] = rh * 3 + rw;
    }
    __syncthreads();

    // cosine-normalize rows (q also absorbs the logit scale)
    if (tid < 2 * N) {
        float* arr = (tid < N) ? qs : ks;
        int r = (tid < N) ? tid : tid - N;
        float ssum = 0.0f;
        #pragma unroll
        for (int d = 0; d < HD; ++d) { float u = arr[r * HD + d]; ssum += u * u; }
        float inv = 1.0f / fmaxf(sqrtf(ssum), 1e-12f);
        if (tid < N) inv *= scale_s;
        #pragma unroll
        for (int d = 0; d < HD; ++d) arr[r * HD + d] *= inv;
    }
    __syncthreads();

    // logits + CPB bias + shift mask
    for (int l = tid; l < N * N; l += blockDim.x) {
        int i = l / N, j = l % N;
        float dot = 0.0f;
        #pragma unroll
        for (int d = 0; d < HD; ++d) dot += qs[i * HD + d] * ks[j * HD + d];
        int idx = ((i / WS - j / WS) + WS - 1) * (2 * WS - 1)
                + ((i % WS - j % WS) + WS - 1);
        float b = g_cpb[idx * NH + h];
        float sig = 16.0f / (1.0f + expf(-b));
        float m = (rgn[i] != rgn[j]) ? -100.0f : 0.0f;
        lg[l] = dot + sig + m;
    }
    __syncthreads();

    // row softmax
    if (tid < N) {
        float mx = -1e30f;
        for (int j = 0; j < N; ++j) mx = fmaxf(mx, lg[tid * N + j]);
        float s = 0.0f;
        for (int j = 0; j < N; ++j) {
            float e = expf(lg[tid * N + j] - mx);
            lg[tid * N + j] = e; s += e;
        }
        float inv = 1.0f / s;
        for (int j = 0; j < N; ++j) lg[tid * N + j] *= inv;
    }
    __syncthreads();

    // out = attn @ v  -> write into g_win (window layout, head-interleaved)
    for (int e = tid; e < N * HD; e += blockDim.x) {
        int i = e / HD, d = e % HD;
        float a = 0.0f;
        #pragma unroll
        for (int j = 0; j < N; ++j) a += lg[i * N + j] * vs[j * HD + d];
        g_win[(size_t)(bw * N + i) * C + h * HD + d] = a;
    }
}

// ---------------- block-wide sum over 192 threads ---------------------------
__device__ __forceinline__ float block_sum192(float v, float* red) {
    #pragma unroll
    for (int o = 16; o > 0; o >>= 1) v += __shfl_down_sync(0xffffffffu, v, o);
    int wid = threadIdx.x >> 5;
    if ((threadIdx.x & 31) == 0) red[wid] = v;
    __syncthreads();
    float s = red[0] + red[1] + red[2] + red[3] + red[4] + red[5];
    __syncthreads();
    return s;
}

// hidden[dst] = x[dst] + LN1(proj[t]), with window-reverse + un-shift scatter
__global__ __launch_bounds__(192)
void postattn_kernel(const float* __restrict__ x,
                     const float* __restrict__ g1, const float* __restrict__ b1) {
    __shared__ float red[6];
    int t = blockIdx.x, c = threadIdx.x;
    int bw = t / N, n = t % N;
    int b  = bw / NW, w_ = bw % NW;
    int wy = w_ / WG, wx = w_ % WG;
    int hh = wy * WS + n / WS, ww = wx * WS + n % WS;
    int oh = (hh + SS) % Hh, ow = (ww + SS) % Ww;
    size_t dst = ((size_t)(b * Hh + oh) * Ww + ow) * C;

    float v = g_q[(size_t)t * C + c];          // proj output row
    float mean = block_sum192(v, red) * (1.0f / C);
    float dv = v - mean;
    float var = block_sum192(dv * dv, red) * (1.0f / C);
    float ln = dv * rsqrtf(var + EPS) * g1[c] + b1[c];
    g_k[dst + c] = x[dst + c] + ln;            // hidden (natural layout)
}

// out[t] = hidden[t] + LN2(mlp[t])
__global__ __launch_bounds__(192)
void final_kernel(const float* __restrict__ g2, const float* __restrict__ b2,
                  float* __restrict__ out) {
    __shared__ float red[6];
    int t = blockIdx.x, c = threadIdx.x;
    float v = g_v[(size_t)t * C + c];          // mlp output row
    float mean = block_sum192(v, red) * (1.0f / C);
    float dv = v - mean;
    float var = block_sum192(dv * dv, red) * (1.0f / C);
    float ln = dv * rsqrtf(var + EPS) * g2[c] + b2[c];
    out[(size_t)t * C + c] = g_k[(size_t)t * C + c] + ln;
}

} // namespace

// ============================================================================
extern "C" void kernel_launch(void* const* d_in, const int* in_sizes, int n_in,
                              void* d_out, int out_size) {
    const float* x      = (const float*)d_in[0];
    const float* ln1_g  = (const float*)d_in[1];
    const float* ln1_b  = (const float*)d_in[2];
    const float* ln2_g  = (const float*)d_in[3];
    const float* ln2_b  = (const float*)d_in[4];
    const float* q_w    = (const float*)d_in[5];
    const float* q_b    = (const float*)d_in[6];
    const float* k_w    = (const float*)d_in[7];
    const float* v_w    = (const float*)d_in[8];
    const float* v_b    = (const float*)d_in[9];
    const float* p_w    = (const float*)d_in[10];
    const float* p_b    = (const float*)d_in[11];
    const float* lscale = (const float*)d_in[12];
    const float* cpb_w0 = (const float*)d_in[13];
    const float* cpb_b0 = (const float*)d_in[14];
    const float* cpb_w1 = (const float*)d_in[15];
    const float* fc1_w  = (const float*)d_in[16];
    const float* fc1_b  = (const float*)d_in[17];
    const float* fc2_w  = (const float*)d_in[18];
    const float* fc2_b  = (const float*)d_in[19];
    float* out = (float*)d_out;

    float *p_win, *p_q, *p_k, *p_v, *p_m1;
    cudaGetSymbolAddress((void**)&p_win, g_win);
    cudaGetSymbolAddress((void**)&p_q,   g_q);
    cudaGetSymbolAddress((void**)&p_k,   g_k);
    cudaGetSymbolAddress((void**)&p_v,   g_v);
    cudaGetSymbolAddress((void**)&p_m1,  g_mlp1);

    // 1) CPB bias table + head scales
    cpb_kernel<<<169, 256>>>(cpb_w0, cpb_b0, cpb_w1, lscale);

    // 2) cyclic shift + window partition
    gather_kernel<<<T, C>>>(x);

    // 3-5) QKV GEMMs (win @ W [+ b])
    dim3 gC(C / BN, T / BM);
    sgemm_kernel<<<gC, 128>>>(p_win, q_w, q_b,     p_q, T, C, C, 0);
    sgemm_kernel<<<gC, 128>>>(p_win, k_w, nullptr, p_k, T, C, C, 0);
    sgemm_kernel<<<gC, 128>>>(p_win, v_w, v_b,     p_v, T, C, C, 0);

    // 6) fused attention (writes attn output into g_win)
    attn_kernel<<<BW * NH, 256>>>();

    // 7) output projection
    sgemm_kernel<<<gC, 128>>>(p_win, p_w, p_b, p_q, T, C, C, 0);

    // 8) window reverse + un-shift + LN1 + residual -> hidden (g_k)
    postattn_kernel<<<T, C>>>(x, ln1_g, ln1_b);

    // 9) fc1 + GELU
    dim3 gF1(C4 / BN, T / BM);
    sgemm_kernel<<<gF1, 128>>>(p_k, fc1_w, fc1_b, p_m1, T, C4, C, 1);

    // 10) fc2
    sgemm_kernel<<<gC, 128>>>(p_m1, fc2_w, fc2_b, p_v, T, C, C4, 0);

    // 11) hidden + LN2(mlp) -> out
    final_kernel<<<T, C>>>(ln2_g, ln2_b, out);
}

// round 2
// speedup vs baseline: 1.0007x; 1.0007x over previous
#include <cuda_runtime.h>
#include <math.h>

namespace {

constexpr int Bb  = 8;
constexpr int Hh  = 112;
constexpr int Ww  = 112;
constexpr int C   = 192;
constexpr int NH  = 6;
constexpr int HD  = 32;      // C / NH
constexpr int WS  = 7;
constexpr int SS  = 3;
constexpr int N   = 49;      // WS*WS
constexpr int WG  = Hh / WS; // 16
constexpr int NW  = WG * WG; // 256
constexpr int BW  = Bb * NW; // 2048
constexpr int T   = BW * N;  // 100352 tokens
constexpr int C4  = 4 * C;   // 768
constexpr float EPS    = 1e-5f;
constexpr float LOG100 = 4.605170185988091f;

// ---------------- scratch (static device globals; no allocation) -----------
__device__ float g_win [(size_t)T * C];   // gathered windows; later attn output
__device__ float g_q   [(size_t)T * C];   // q; later proj output
__device__ float g_k   [(size_t)T * C];   // k; later hidden
__device__ float g_v   [(size_t)T * C];   // v; later mlp output
__device__ float g_mlp1[(size_t)T * C4];  // fc1 output
__device__ float g_cpb [169 * NH];        // CPB MLP output table (169 x NH)
__device__ float g_scl [NH];              // per-head logit scale

// ---------------- CPB bias table MLP: (169,2)->512(relu)->NH ---------------
__global__ void cpb_kernel(const float* __restrict__ w0, const float* __restrict__ b0,
                           const float* __restrict__ w1, const float* __restrict__ ls) {
    int r   = blockIdx.x;     // 0..168
    int tid = threadIdx.x;    // 256 threads
    __shared__ float part[256][NH];

    int ri = r / 13, rj = r % 13;
    float t0 = (ri - 6) * (8.0f / 6.0f);
    float t1 = (rj - 6) * (8.0f / 6.0f);
    float v0 = copysignf(log2f(fabsf(t0) + 1.0f) * (1.0f / 3.0f), t0);
    float v1 = copysignf(log2f(fabsf(t1) + 1.0f) * (1.0f / 3.0f), t1);

    float acc[NH];
    #pragma unroll
    for (int h = 0; h < NH; ++h) acc[h] = 0.0f;
    for (int j = tid; j < 512; j += 256) {
        float hv = fmaxf(v0 * w0[j] + v1 * w0[512 + j] + b0[j], 0.0f);
        #pragma unroll
        for (int h = 0; h < NH; ++h) acc[h] += hv * w1[j * NH + h];
    }
    #pragma unroll
    for (int h = 0; h < NH; ++h) part[tid][h] = acc[h];
    __syncthreads();
    if (tid < NH) {
        float s = 0.0f;
        for (int i = 0; i < 256; ++i) s += part[i][tid];
        g_cpb[r * NH + tid] = s;
        if (r == 0) g_scl[tid] = expf(fminf(ls[tid], LOG100));
    }
}

// ---------------- cyclic shift + window partition gather -------------------
__global__ void gather_kernel(const float* __restrict__ x) {
    int t  = blockIdx.x;          // window-layout token
    int bw = t / N, n = t % N;
    int b  = bw / NW, w_ = bw % NW;
    int wy = w_ / WG, wx = w_ % WG;
    int hh = wy * WS + n / WS, ww = wx * WS + n % WS;
    int oh = (hh + SS) % Hh, ow = (ww + SS) % Ww;
    size_t src = ((size_t)(b * Hh + oh) * Ww + ow) * C;
    g_win[(size_t)t * C + threadIdx.x] = x[src + threadIdx.x];
}

// ---------------- fp32 SGEMM: C = act(A@B + bias) --------------------------
// A: MxK row-major, B: KxN row-major. M%128==0, N%64==0, K%16==0.
constexpr int BM = 128, BN = 64, BK = 16, TM = 8, TN = 8;

__device__ __forceinline__ float gelu_tanh(float v) {
    return 0.5f * v * (1.0f + tanhf(0.7978845608028654f * (v + 0.044715f * v * v * v)));
}

__global__ __launch_bounds__(128, 4)
void sgemm_kernel(const float* __restrict__ A, const float* __restrict__ B,
                  const float* __restrict__ bias, float* __restrict__ Cmat,
                  int M, int Nn, int K, int act) {
    __shared__ float As[BK][BM + 1];
    __shared__ float Bs[BK][BN];

    int tid = threadIdx.x;                 // 0..127
    int bm  = blockIdx.y * BM;
    int bn  = blockIdx.x * BN;
    int trow = (tid >> 3) * TM;            // 16 groups of 8
    int tcol = (tid & 7) * TN;

    float acc[TM][TN];
    #pragma unroll
    for (int i = 0; i < TM; ++i)
        #pragma unroll
        for (int j = 0; j < TN; ++j) acc[i][j] = 0.0f;

    for (int kt = 0; kt < K; kt += BK) {
        #pragma unroll
        for (int i = 0; i < 4; ++i) {              // A tile: 128x16
            int idx = tid + i * 128;
            int row = idx >> 2;
            int k4  = (idx & 3) * 4;
            float4 a = *reinterpret_cast<const float4*>(
                &A[(size_t)(bm + row) * K + kt + k4]);
            As[k4 + 0][row] = a.x; As[k4 + 1][row] = a.y;
            As[k4 + 2][row] = a.z; As[k4 + 3][row] = a.w;
        }
        #pragma unroll
        for (int i = 0; i < 2; ++i) {              // B tile: 16x64
            int idx = tid + i * 128;
            int row = idx >> 4;
            int c4  = (idx & 15) * 4;
            *reinterpret_cast<float4*>(&Bs[row][c4]) =
                *reinterpret_cast<const float4*>(&B[(size_t)(kt + row) * Nn + bn + c4]);
        }
        __syncthreads();
        #pragma unroll
        for (int kk = 0; kk < BK; ++kk) {
            float af[TM], bf[TN];
            #pragma unroll
            for (int i = 0; i < TM; ++i) af[i] = As[kk][trow + i];
            #pragma unroll
            for (int j = 0; j < TN; ++j) bf[j] = Bs[kk][tcol + j];
            #pragma unroll
            for (int i = 0; i < TM; ++i)
                #pragma unroll
                for (int j = 0; j < TN; ++j) acc[i][j] += af[i] * bf[j];
        }
        __syncthreads();
    }

    #pragma unroll
    for (int i = 0; i < TM; ++i) {
        size_t rbase = (size_t)(bm + trow + i) * Nn + bn + tcol;
        #pragma unroll
        for (int j = 0; j < TN; ++j) {
            float v = acc[i][j];
            if (bias) v += bias[bn + tcol + j];
            if (act == 1) v = gelu_tanh(v);
            Cmat[rbase + j] = v;
        }
    }
}

// ---------------- fused per-(window,head) attention -------------------------
__global__ __launch_bounds__(256)
void attn_kernel() {
    int blk = blockIdx.x;          // 0..BW*NH-1
    int bw  = blk / NH, h = blk % NH;
    int tid = threadIdx.x;

    __shared__ float qs[N * HD], ks[N * HD], vs[N * HD];
    __shared__ float lg[N * N];
    __shared__ int   rgn[N];
    __shared__ float scale_s;

    if (tid == 0) scale_s = g_scl[h];

    for (int e = tid; e < N * HD; e += blockDim.x) {
        int n = e / HD, d = e % HD;
        size_t base = (size_t)(bw * N + n) * C + h * HD + d;
        qs[e] = g_q[base]; ks[e] = g_k[base]; vs[e] = g_v[base];
    }
    if (tid < N) {
        int w_ = bw % NW, wy = w_ / WG, wx = w_ % WG;
        int gh = wy * WS + tid / WS, gw = wx * WS + tid % WS;
        int rh = gh < Hh - WS ? 0 : (gh < Hh - SS ? 1 : 2);
        int rw = gw < Ww - WS ? 0 : (gw < Ww - SS ? 1 : 2);
        rgn[tid] = rh * 3 + rw;
    }
    __syncthreads();

    // cosine-normalize rows (q also absorbs the logit scale)
    if (tid < 2 * N) {
        float* arr = (tid < N) ? qs : ks;
        int r = (tid < N) ? tid : tid - N;
        float ssum = 0.0f;
        #pragma unroll
        for (int d = 0; d < HD; ++d) { float u = arr[r * HD + d]; ssum += u * u; }
        float inv = 1.0f / fmaxf(sqrtf(ssum), 1e-12f);
        if (tid < N) inv *= scale_s;
        #pragma unroll
        for (int d = 0; d < HD; ++d) arr[r * HD + d] *= inv;
    }
    __syncthreads();

    // logits + CPB bias + shift mask
    for (int l = tid; l < N * N; l += blockDim.x) {
        int i = l / N, j = l % N;
        float dot = 0.0f;
        #pragma unroll
        for (int d = 0; d < HD; ++d) dot += qs[i * HD + d] * ks[j * HD + d];
        int idx = ((i / WS - j / WS) + WS - 1) * (2 * WS - 1)
                + ((i % WS - j % WS) + WS - 1);
        float b = g_cpb[idx * NH + h];
        float sig = 16.0f / (1.0f + expf(-b));
        float m = (rgn[i] != rgn[j]) ? -100.0f : 0.0f;
        lg[l] = dot + sig + m;
    }
    __syncthreads();

    // row softmax
    if (tid < N) {
        float mx = -1e30f;
        for (int j = 0; j < N; ++j) mx = fmaxf(mx, lg[tid * N + j]);
        float s = 0.0f;
        for (int j = 0; j < N; ++j) {
            float e = expf(lg[tid * N + j] - mx);
            lg[tid * N + j] = e; s += e;
        }
        float inv = 1.0f / s;
        for (int j = 0; j < N; ++j) lg[tid * N + j] *= inv;
    }
    __syncthreads();

    // out = attn @ v  -> write into g_win (window layout, head-interleaved)
    for (int e = tid; e < N * HD; e += blockDim.x) {
        int i = e / HD, d = e % HD;
        float a = 0.0f;
        #pragma unroll
        for (int j = 0; j < N; ++j) a += lg[i * N + j] * vs[j * HD + d];
        g_win[(size_t)(bw * N + i) * C + h * HD + d] = a;
    }
}

// ---------------- block-wide sum over 192 threads ---------------------------
__device__ __forceinline__ float block_sum192(float v, float* red) {
    #pragma unroll
    for (int o = 16; o > 0; o >>= 1) v += __shfl_down_sync(0xffffffffu, v, o);
    int wid = threadIdx.x >> 5;
    if ((threadIdx.x & 31) == 0) red[wid] = v;
    __syncthreads();
    float s = red[0] + red[1] + red[2] + red[3] + red[4] + red[5];
    __syncthreads();
    return s;
}

// hidden[dst] = x[dst] + LN1(proj[t]), with window-reverse + un-shift scatter
__global__ __launch_bounds__(192)
void postattn_kernel(const float* __restrict__ x,
                     const float* __restrict__ g1, const float* __restrict__ b1) {
    __shared__ float red[6];
    int t = blockIdx.x, c = threadIdx.x;
    int bw = t / N, n = t % N;
    int b  = bw / NW, w_ = bw % NW;
    int wy = w_ / WG, wx = w_ % WG;
    int hh = wy * WS + n / WS, ww = wx * WS + n % WS;
    int oh = (hh + SS) % Hh, ow = (ww + SS) % Ww;
    size_t dst = ((size_t)(b * Hh + oh) * Ww + ow) * C;

    float v = g_q[(size_t)t * C + c];          // proj output row
    float mean = block_sum192(v, red) * (1.0f / C);
    float dv = v - mean;
    float var = block_sum192(dv * dv, red) * (1.0f / C);
    float ln = dv * rsqrtf(var + EPS) * g1[c] + b1[c];
    g_k[dst + c] = x[dst + c] + ln;            // hidden (natural layout)
}

// out[t] = hidden[t] + LN2(mlp[t])
__global__ __launch_bounds__(192)
void final_kernel(const float* __restrict__ g2, const float* __restrict__ b2,
                  float* __restrict__ out) {
    __shared__ float red[6];
    int t = blockIdx.x, c = threadIdx.x;
    float v = g_v[(size_t)t * C + c];          // mlp output row
    float mean = block_sum192(v, red) * (1.0f / C);
    float dv = v - mean;
    float var = block_sum192(dv * dv, red) * (1.0f / C);
    float ln = dv * rsqrtf(var + EPS) * g2[c] + b2[c];
    out[(size_t)t * C + c] = g_k[(size_t)t * C + c] + ln;
}

} // namespace

// ============================================================================
extern "C" void kernel_launch(void* const* d_in, const int* in_sizes, int n_in,
                              void* d_out, int out_size) {
    const float* x      = (const float*)d_in[0];
    const float* ln1_g  = (const float*)d_in[1];
    const float* ln1_b  = (const float*)d_in[2];
    const float* ln2_g  = (const float*)d_in[3];
    const float* ln2_b  = (const float*)d_in[4];
    const float* q_w    = (const float*)d_in[5];
    const float* q_b    = (const float*)d_in[6];
    const float* k_w    = (const float*)d_in[7];
    const float* v_w    = (const float*)d_in[8];
    const float* v_b    = (const float*)d_in[9];
    const float* p_w    = (const float*)d_in[10];
    const float* p_b    = (const float*)d_in[11];
    const float* lscale = (const float*)d_in[12];
    const float* cpb_w0 = (const float*)d_in[13];
    const float* cpb_b0 = (const float*)d_in[14];
    const float* cpb_w1 = (const float*)d_in[15];
    const float* fc1_w  = (const float*)d_in[16];
    const float* fc1_b  = (const float*)d_in[17];
    const float* fc2_w  = (const float*)d_in[18];
    const float* fc2_b  = (const float*)d_in[19];
    float* out = (float*)d_out;

    float *p_win, *p_q, *p_k, *p_v, *p_m1;
    cudaGetSymbolAddress((void**)&p_win, g_win);
    cudaGetSymbolAddress((void**)&p_q,   g_q);
    cudaGetSymbolAddress((void**)&p_k,   g_k);
    cudaGetSymbolAddress((void**)&p_v,   g_v);
    cudaGetSymbolAddress((void**)&p_m1,  g_mlp1);

    // 1) CPB bias table + head scales
    cpb_kernel<<<169, 256>>>(cpb_w0, cpb_b0, cpb_w1, lscale);

    // 2) cyclic shift + window partition
    gather_kernel<<<T, C>>>(x);

    // 3-5) QKV GEMMs (win @ W [+ b])
    dim3 gC(C / BN, T / BM);
    sgemm_kernel<<<gC, 128>>>(p_win, q_w, q_b,     p_q, T, C, C, 0);
    sgemm_kernel<<<gC, 128>>>(p_win, k_w, nullptr, p_k, T, C, C, 0);
    sgemm_kernel<<<gC, 128>>>(p_win, v_w, v_b,     p_v, T, C, C, 0);

    // 6) fused attention (writes attn output into g_win)
    attn_kernel<<<BW * NH, 256>>>();

    // 7) output projection
    sgemm_kernel<<<gC, 128>>>(p_win, p_w, p_b, p_q, T, C, C, 0);

    // 8) window reverse + un-shift + LN1 + residual -> hidden (g_k)
    postattn_kernel<<<T, C>>>(x, ln1_g, ln1_b);

    // 9) fc1 + GELU
    dim3 gF1(C4 / BN, T / BM);
    sgemm_kernel<<<gF1, 128>>>(p_k, fc1_w, fc1_b, p_m1, T, C4, C, 1);

    // 10) fc2
    sgemm_kernel<<<gC, 128>>>(p_m1, fc2_w, fc2_b, p_v, T, C, C4, 0);

    // 11) hidden + LN2(mlp) -> out
    final_kernel<<<T, C>>>(ln2_g, ln2_b, out);
}